// round 16
// baseline (speedup 1.0000x reference)
#include <cuda_runtime.h>
#include <cuda_bf16.h>

// QuantumCBOW: B=16384, S=10, DIM=8, TRIL=36.
// R16 = R14 (4 lanes/element, minimal redundancy — correctness-validated at
// rel 1.57e-4) with the spill bug fixed:
//  * __launch_bounds__(64,6) -> 168-reg cap (R14's (64,7) forced 128 regs ->
//    spills -> alu 38.8% of spill-address IMADs, 33us)
//  * sigm[36] array deleted: lanes 2,3 keep the third density in tmp and use
//    it directly as sigma (saves 36 live regs + 36 MULs)
// Chip work ~6.4M warp-instrs (-30% vs R12) at 3.46 warps/SMSP.

#define QC_DIM  8
#define QC_TRIL 36
#define QC_S    10

__device__ __forceinline__ constexpr int sidx(int i, int j) { return i * (i + 1) / 2 + j; }

// density(row) -> dst[36] (lower-tri), trace-normalized, eps'd.
__device__ __forceinline__ void dens_compute(const float* __restrict__ row, float* dst) {
    float L[QC_TRIL];
    const float4* r4 = reinterpret_cast<const float4*>(row);  // 36*4B rows, 16B aligned
#pragma unroll
    for (int v = 0; v < 9; v++) {
        float4 t = r4[v];
        L[4 * v + 0] = t.x; L[4 * v + 1] = t.y;
        L[4 * v + 2] = t.z; L[4 * v + 3] = t.w;
    }
#pragma unroll
    for (int i = 0; i < QC_DIM; i++) {
        const int d = sidx(i, i);
        L[d] = fmaxf(L[d], 1e-4f);
    }
    float tr = 0.f;
#pragma unroll
    for (int i = 0; i < QC_TRIL; i++) tr = fmaf(L[i], L[i], tr);
    const float inv = __fdividef(1.0f, tr + 1.7e-5f);
#pragma unroll
    for (int i = 0; i < QC_DIM; i++) {
#pragma unroll
        for (int j = 0; j <= i; j++) {
            float s = 0.f;
#pragma unroll
            for (int k = 0; k <= j; k++)
                s = fmaf(L[sidx(i, k)], L[sidx(j, k)], s);
            if (i == j) s += 2e-6f;  // eps + corr
            dst[sidx(i, j)] = s * inv;
        }
    }
}

// acc += wgt * density(row)
__device__ __forceinline__ void add_density(const float* __restrict__ row, float* acc, float wgt) {
    float tmp[QC_TRIL];
    dens_compute(row, tmp);
#pragma unroll
    for (int i = 0; i < QC_TRIL; i++) acc[i] = fmaf(wgt, tmp[i], acc[i]);
}

// Lower-tri element of Cb with compile-time zero padding.
#define CEL(k, j) (((k) >= (j)) ? Cb[(k) * ((k) + 1) / 2 + (j)] : 0.0f)

// One-sided rotation of own column against partner snapshot (R5/R14-validated:
// both lanes see (n, pn) swapped -> dd flips sign -> consistent updates).
#define OS_ROT(colx, px, nx, pnx) do {                                         \
    float g = 0.f;                                                             \
    _Pragma("unroll")                                                          \
    for (int k = 0; k < QC_DIM; k++) g = fmaf(colx[k], px[k], g);              \
    const float dd = (pnx) - (nx);                                             \
    const float a2 = 2.0f * g;                                                 \
    const float vv = fmaf(dd, dd, fmaf(a2, a2, 1e-30f));                       \
    const float u  = vv * rsqrtf(vv);                                          \
    const float t  = __fdividef(a2 * copysignf(1.0f, dd), fabsf(dd) + u);      \
    const float c  = rsqrtf(fmaf(t, t, 1.0f));                                 \
    const float s  = t * c;                                                    \
    _Pragma("unroll")                                                          \
    for (int k = 0; k < QC_DIM; k++)                                           \
        colx[k] = fmaf(c, colx[k], -s * px[k]);                                \
    nx = fmaf(-t, g, nx);                                                      \
} while (0)

// Local rotation of the pair (ca, cb) owned by this lane (R5/R14-validated).
#define OS_LOCAL() do {                                                        \
    float g = 0.f;                                                             \
    _Pragma("unroll")                                                          \
    for (int k = 0; k < QC_DIM; k++) g = fmaf(ca[k], cb[k], g);                \
    const float dd = nb - na;                                                  \
    const float a2 = 2.0f * g;                                                 \
    const float vv = fmaf(dd, dd, fmaf(a2, a2, 1e-30f));                       \
    const float u  = vv * rsqrtf(vv);                                          \
    const float t  = __fdividef(a2 * copysignf(1.0f, dd), fabsf(dd) + u);      \
    const float c  = rsqrtf(fmaf(t, t, 1.0f));                                 \
    const float s  = t * c;                                                    \
    _Pragma("unroll")                                                          \
    for (int k = 0; k < QC_DIM; k++) {                                         \
        const float x = ca[k], y = cb[k];                                      \
        ca[k] = fmaf(c, x, -s * y);                                            \
        cb[k] = fmaf(s, x,  c * y);                                            \
    }                                                                          \
    na = fmaf(-t, g, na);                                                      \
    nb = fmaf( t, g, nb);                                                      \
} while (0)

// Cross round with lane l^m (m in {1,2,3} stays inside the 4-lane group).
// CROSSED=0: (ca<->p.ca, cb<->p.cb); CROSSED=1: (ca<->p.cb, cb<->p.ca).
#define OS_CROSS(m, CROSSED) do {                                              \
    float pa[QC_DIM], pb[QC_DIM];                                              \
    _Pragma("unroll")                                                          \
    for (int k = 0; k < QC_DIM; k++) {                                         \
        pa[k] = __shfl_xor_sync(0xffffffffu, (CROSSED) ? cb[k] : ca[k], (m));  \
        pb[k] = __shfl_xor_sync(0xffffffffu, (CROSSED) ? ca[k] : cb[k], (m));  \
    }                                                                          \
    float pna = __shfl_xor_sync(0xffffffffu, (CROSSED) ? nb : na, (m));        \
    float pnb = __shfl_xor_sync(0xffffffffu, (CROSSED) ? na : nb, (m));        \
    OS_ROT(ca, pa, na, pna);                                                   \
    OS_ROT(cb, pb, nb, pnb);                                                   \
} while (0)

__global__ void __launch_bounds__(64, 6)
qcbow_kernel(const int* __restrict__ contexts,
             const int* __restrict__ targets,
             const float* __restrict__ emb,
             float* __restrict__ out,
             int B) {
    const int gt = blockIdx.x * 64 + threadIdx.x;
    int e = gt >> 2;
    const int l = gt & 3;              // lane within 4-lane group
    const bool valid = (e < B);
    if (!valid) e = 0;                 // clamp (keep shfl groups intact)

    // ---- token assignment: lanes 0,1 -> {l, l+4, l+8}; lanes 2,3 -> {l, l+4} + target
    const bool hasT3 = (l < 2);
    const int tok0 = contexts[e * QC_S + l];
    const int tok1 = contexts[e * QC_S + l + 4];
    const int tok2 = hasT3 ? contexts[e * QC_S + l + 8] : targets[e];

    // ---- two ctx densities ----
    float ctxp[QC_TRIL];
#pragma unroll
    for (int i = 0; i < QC_TRIL; i++) ctxp[i] = 0.f;
    const float m0 = (tok0 != 0) ? 1.0f : 0.0f;
    const float m1 = (tok1 != 0) ? 1.0f : 0.0f;
    float cnt = m0 + m1;
    add_density(emb + (long)tok0 * QC_TRIL, ctxp, m0);
    add_density(emb + (long)tok1 * QC_TRIL, ctxp, m1);

    // ---- third density: ctx token (lanes 0,1) or sigma (lanes 2,3) ----
    // tmp stays live: lanes 2,3 use it directly as sigma below.
    const float mc2 = hasT3 ? ((tok2 != 0) ? 1.0f : 0.0f) : 0.0f;  // ctx weight
    cnt += mc2;
    float tmp[QC_TRIL];
    dens_compute(emb + (long)tok2 * QC_TRIL, tmp);
#pragma unroll
    for (int i = 0; i < QC_TRIL; i++)
        ctxp[i] = fmaf(mc2, tmp[i], ctxp[i]);

    // ---- butterfly: full ctx + cnt across the 4-lane group ----
#pragma unroll
    for (int i = 0; i < QC_TRIL; i++) ctxp[i] += __shfl_xor_sync(0xffffffffu, ctxp[i], 1);
    cnt += __shfl_xor_sync(0xffffffffu, cnt, 1);
#pragma unroll
    for (int i = 0; i < QC_TRIL; i++) ctxp[i] += __shfl_xor_sync(0xffffffffu, ctxp[i], 2);
    cnt += __shfl_xor_sync(0xffffffffu, cnt, 2);
    const float ic = __fdividef(1.0f, cnt);  // cnt==0 -> inf, matches ref 0/0

    // ---- my Cholesky target: lanes 0,1 -> ctx/cnt + 1e-6 I; lanes 2,3 -> sigma ----
    float mat[QC_TRIL];
#pragma unroll
    for (int i = 0; i < QC_TRIL; i++) {
        const float cv = ctxp[i] * ic;
        mat[i] = hasT3 ? cv : tmp[i];
    }
    const float dadd = hasT3 ? 1e-6f : 0.0f;
#pragma unroll
    for (int d = 0; d < QC_DIM; d++) mat[sidx(d, d)] += dadd;

    // ---- in-place Cholesky of mat (uniform code, per-lane data) ----
#pragma unroll
    for (int j = 0; j < QC_DIM; j++) {
        float d = mat[sidx(j, j)];
#pragma unroll
        for (int k = 0; k < j; k++) d = fmaf(-mat[sidx(j, k)], mat[sidx(j, k)], d);
        d = fmaxf(d, 1e-20f);
        const float icjj = rsqrtf(d);
        mat[sidx(j, j)] = d * icjj;
#pragma unroll
        for (int i = j + 1; i < QC_DIM; i++) {
            float v = mat[sidx(i, j)];
#pragma unroll
            for (int k = 0; k < j; k++) v = fmaf(-mat[sidx(i, k)], mat[sidx(j, k)], v);
            mat[sidx(i, j)] = v * icjj;
        }
    }
    // lanes 0,1: mat = C (CC^T = ctx+1e-6I); lanes 2,3: mat = S (SS^T = sigma)

    // ---- distribute factors: C from lane 0, S from lane 2 (width-4 bcast) ----
    float Cb[QC_TRIL], Sb[QC_TRIL];
#pragma unroll
    for (int i = 0; i < QC_TRIL; i++) {
        Cb[i] = __shfl_sync(0xffffffffu, mat[i], 0, 4);
        Sb[i] = __shfl_sync(0xffffffffu, mat[i], 2, 4);
    }

    // ---- my two columns of A = S^T C  (cols l and l+4) ----
    float Cl[QC_DIM], Cm[QC_DIM];
#pragma unroll
    for (int k = 0; k < QC_DIM; k++) {
        Cl[k] = (l == 0) ? CEL(k, 0) : (l == 1) ? CEL(k, 1) : (l == 2) ? CEL(k, 2) : CEL(k, 3);
        Cm[k] = (l == 0) ? CEL(k, 4) : (l == 1) ? CEL(k, 5) : (l == 2) ? CEL(k, 6) : CEL(k, 7);
    }
    float ca[QC_DIM], cb[QC_DIM];
#pragma unroll
    for (int i = 0; i < QC_DIM; i++) {
        float sa = 0.f, sb = 0.f;
#pragma unroll
        for (int k = i; k < QC_DIM; k++) {
            const float sv = Sb[sidx(k, i)];
            sa = fmaf(sv, Cl[k], sa);
            sb = fmaf(sv, Cm[k], sb);
        }
        ca[i] = sa; cb[i] = sb;
    }

    // ---- one-sided Jacobi, 3 sweeps x (1 local + 6 cross) rounds ----
    float na, nb;
#pragma unroll 1
    for (int sweep = 0; sweep < 3; sweep++) {
        na = 0.f; nb = 0.f;
#pragma unroll
        for (int k = 0; k < QC_DIM; k++) {
            na = fmaf(ca[k], ca[k], na);
            nb = fmaf(cb[k], cb[k], nb);
        }
        OS_LOCAL();            // (l, l+4)
        OS_CROSS(1, 0);
        OS_CROSS(1, 1);
        OS_CROSS(2, 0);
        OS_CROSS(2, 1);
        OS_CROSS(3, 0);
        OS_CROSS(3, 1);
    }

    // ---- f = sum sqrt(colnorm^2 + eps); reduce over 4 lanes ----
    {
        float s0 = 0.f, s1 = 0.f;
#pragma unroll
        for (int k = 0; k < QC_DIM; k++) {
            s0 = fmaf(ca[k], ca[k], s0);
            s1 = fmaf(cb[k], cb[k], s1);
        }
        const float x0 = s0 + 1e-6f;
        const float x1 = s1 + 1e-6f;
        float p = fmaf(x0, rsqrtf(x0), x1 * rsqrtf(x1));
        p += __shfl_xor_sync(0xffffffffu, p, 1);
        p += __shfl_xor_sync(0xffffffffu, p, 2);
        if (valid && l == 0) {
            float f = fminf(p, 1.0f);
            f = fmaxf(f, 1e-8f);
            out[e] = -logf(f);
        }
    }
}

extern "C" void kernel_launch(void* const* d_in, const int* in_sizes, int n_in,
                              void* d_out, int out_size) {
    const int*   contexts = (const int*)d_in[0];   // [B, 10] int32
    const int*   targets  = (const int*)d_in[1];   // [B] int32
    const float* emb      = (const float*)d_in[2]; // [V, 36] float32
    float*       out      = (float*)d_out;         // [B] float32
    const int B = in_sizes[1];                     // 16384
    const int threads = 64;
    const int blocks = (4 * B + threads - 1) / threads;   // 1024 blocks
    qcbow_kernel<<<blocks, threads>>>(contexts, targets, emb, out, B);
}

// round 17
// speedup vs baseline: 1.8618x; 1.8618x over previous
#include <cuda_runtime.h>
#include <cuda_bf16.h>

// QuantumCBOW: B=16384, S=10, DIM=8, TRIL=36.
// R17 = R12 front half + R9 back half:
//  * density phase split over a 2-lane pair (sigma on both lanes, 5 ctx
//    tokens each, one butterfly) — R12-validated, clean 168-reg compile
//  * then BOTH lanes redundantly run R9's validated packed two-sided Jacobi
//    pipeline (Cholesky -> W = C^T sigma C -> 3 sweeps). Redundancy costs the
//    warp nothing vs one lane working; kills the shfl-heavy one-sided cross
//    rounds (9k instr/element -> ~6.2k) and needs zero Jacobi shuffles.
// Chip work ~6.7M warp-instrs (-21% vs R12) at R12's 1.73 warps/SMSP.

#define QC_DIM  8
#define QC_TRIL 36
#define QC_S    10

__device__ __forceinline__ constexpr int sidx(int i, int j) { return i * (i + 1) / 2 + j; }
__device__ __forceinline__ constexpr int symi(int i, int j) { return (i >= j) ? sidx(i, j) : sidx(j, i); }

// Accumulate wgt * normalized-density(row) into acc[36] (lower-tri storage).
__device__ __forceinline__ void add_density(const float* __restrict__ row, float* acc, float wgt) {
    float L[QC_TRIL];
    const float4* r4 = reinterpret_cast<const float4*>(row);  // 36*4B rows, 16B aligned
#pragma unroll
    for (int v = 0; v < 9; v++) {
        float4 t = r4[v];
        L[4 * v + 0] = t.x; L[4 * v + 1] = t.y;
        L[4 * v + 2] = t.z; L[4 * v + 3] = t.w;
    }
#pragma unroll
    for (int i = 0; i < QC_DIM; i++) {
        const int d = sidx(i, i);
        L[d] = fmaxf(L[d], 1e-4f);
    }
    float tr = 0.f;
#pragma unroll
    for (int i = 0; i < QC_TRIL; i++) tr = fmaf(L[i], L[i], tr);
    const float inv = wgt * __fdividef(1.0f, tr + 1.7e-5f);
#pragma unroll
    for (int i = 0; i < QC_DIM; i++) {
#pragma unroll
        for (int j = 0; j <= i; j++) {
            float s = 0.f;
#pragma unroll
            for (int k = 0; k <= j; k++)
                s = fmaf(L[sidx(i, k)], L[sidx(j, k)], s);
            if (i == j) s += 2e-6f;  // eps + corr
            acc[sidx(i, j)] = fmaf(s, inv, acc[sidx(i, j)]);
        }
    }
}

// Packed-symmetric branchless Jacobi rotation on W[36], pair (p,q), p<q.
// (R9-validated: closed-form diagonal, fdividef-based t.)
#define JROT(p, q) do {                                                        \
    const float apq = W[sidx(q, p)];                                           \
    const float dd  = W[sidx(q, q)] - W[sidx(p, p)];                           \
    const float a2  = 2.0f * apq;                                              \
    const float vv  = fmaf(dd, dd, fmaf(a2, a2, 1e-30f));                      \
    const float u   = vv * rsqrtf(vv);                                         \
    const float t   = __fdividef(a2 * copysignf(1.0f, dd), fabsf(dd) + u);     \
    const float c   = rsqrtf(fmaf(t, t, 1.0f));                                \
    const float s   = t * c;                                                   \
    W[sidx(p, p)] = fmaf(-t, apq, W[sidx(p, p)]);                              \
    W[sidx(q, q)] = fmaf( t, apq, W[sidx(q, q)]);                              \
    W[sidx(q, p)] = 0.0f;                                                      \
    _Pragma("unroll")                                                          \
    for (int k = 0; k < QC_DIM; k++) {                                         \
        if (k != p && k != q) {                                                \
            const float akp = W[symi(k, p)];                                   \
            const float akq = W[symi(k, q)];                                   \
            W[symi(k, p)] = fmaf(c, akp, -s * akq);                            \
            W[symi(k, q)] = fmaf(s, akp,  c * akq);                            \
        }                                                                      \
    }                                                                          \
} while (0)

__global__ void __launch_bounds__(128, 2)
qcbow_kernel(const int* __restrict__ contexts,
             const int* __restrict__ targets,
             const float* __restrict__ emb,
             float* __restrict__ out,
             int B) {
    const int gt = blockIdx.x * 128 + threadIdx.x;
    const int e = gt >> 1;
    const int h = gt & 1;
    if (e >= B) return;   // 2B % 128 == 0 -> no partial pairs/warps

    // ---- token ids (row is 8B-aligned: 10 ints = 5 x int2) ----
    int toks[QC_S];
    {
        const int2* c2 = reinterpret_cast<const int2*>(contexts + e * QC_S);
#pragma unroll
        for (int v = 0; v < 5; v++) {
            const int2 t = c2[v];
            toks[2 * v] = t.x; toks[2 * v + 1] = t.y;
        }
    }
    const int tgt = targets[e];

    // ---- sigma density (both lanes; same row -> L1 broadcast) ----
    float sigm[QC_TRIL];
#pragma unroll
    for (int i = 0; i < QC_TRIL; i++) sigm[i] = 0.f;
    add_density(emb + (long)tgt * QC_TRIL, sigm, 1.0f);

    // ---- 5 context densities for this lane: tokens {2k + h} ----
    float ctxp[QC_TRIL];
#pragma unroll
    for (int i = 0; i < QC_TRIL; i++) ctxp[i] = 0.f;
    float cnt = 0.f;
#pragma unroll
    for (int k = 0; k < 5; k++) {
        const int tok = toks[2 * k + h];
        const float m = (tok != 0) ? 1.0f : 0.0f;
        cnt += m;
        add_density(emb + (long)tok * QC_TRIL, ctxp, m);
    }

    // ---- butterfly: full ctx + cnt across the lane pair ----
    cnt += __shfl_xor_sync(0xffffffffu, cnt, 1);
#pragma unroll
    for (int i = 0; i < QC_TRIL; i++)
        ctxp[i] += __shfl_xor_sync(0xffffffffu, ctxp[i], 1);
    {
        const float ic = __fdividef(1.0f, cnt);  // cnt==0 -> inf, matches ref 0/0
#pragma unroll
        for (int i = 0; i < QC_TRIL; i++) ctxp[i] *= ic;
    }

    // ==== from here BOTH lanes redundantly run R9's validated pipeline ====

    // ---- in-place Cholesky of (ctx + 1e-6 I): ctxp becomes C with C C^T ----
#pragma unroll
    for (int j = 0; j < QC_DIM; j++) {
        float d = ctxp[sidx(j, j)] + 1e-6f;
#pragma unroll
        for (int k = 0; k < j; k++) d = fmaf(-ctxp[sidx(j, k)], ctxp[sidx(j, k)], d);
        d = fmaxf(d, 1e-14f);
        const float icjj = rsqrtf(d);
        ctxp[sidx(j, j)] = d * icjj;
#pragma unroll
        for (int i = j + 1; i < QC_DIM; i++) {
            float v = ctxp[sidx(i, j)];
#pragma unroll
            for (int k = 0; k < j; k++) v = fmaf(-ctxp[sidx(i, k)], ctxp[sidx(j, k)], v);
            ctxp[sidx(i, j)] = v * icjj;
        }
    }

    // ---- W = C^T * sigma * C, packed lower-tri (eig(W) = eig((ctx+eps I) sigma)) ----
    float W[QC_TRIL];
#pragma unroll
    for (int j = 0; j < QC_DIM; j++) {
        float tj[QC_DIM];  // column j of T = sigma * C
#pragma unroll
        for (int i = 0; i < QC_DIM; i++) {
            float s = 0.f;
#pragma unroll
            for (int k = j; k < QC_DIM; k++)      // C[k][j] nonzero for k>=j
                s = fmaf(sigm[symi(i, k)], ctxp[sidx(k, j)], s);
            tj[i] = s;
        }
#pragma unroll
        for (int i = 0; i <= j; i++) {            // W[i][j], i<=j -> store at sidx(j,i)
            float s = 0.f;
#pragma unroll
            for (int k = i; k < QC_DIM; k++)      // C[k][i] nonzero for k>=i
                s = fmaf(ctxp[sidx(k, i)], tj[k], s);
            W[sidx(j, i)] = s;
        }
    }

    // ---- eigenvalues-only packed Jacobi, round-robin, 3 sweeps ----
#pragma unroll 1
    for (int sweep = 0; sweep < 3; sweep++) {
        JROT(0, 7); JROT(1, 6); JROT(2, 5); JROT(3, 4);
        JROT(1, 7); JROT(0, 2); JROT(3, 6); JROT(4, 5);
        JROT(2, 7); JROT(1, 3); JROT(0, 4); JROT(5, 6);
        JROT(3, 7); JROT(2, 4); JROT(1, 5); JROT(0, 6);
        JROT(4, 7); JROT(3, 5); JROT(2, 6); JROT(0, 1);
        JROT(5, 7); JROT(4, 6); JROT(0, 3); JROT(1, 2);
        JROT(6, 7); JROT(0, 5); JROT(1, 4); JROT(2, 3);
    }

    // ---- f = sum sqrt(|eig| + eps); out = -log(clip(f)) ----
    float f = 0.f;
#pragma unroll
    for (int i = 0; i < QC_DIM; i++) {
        const float x = fabsf(W[sidx(i, i)]) + 1e-6f;
        f = fmaf(x, rsqrtf(x), f);   // sqrt(x) = x * rsqrt(x), x >= 1e-6
    }
    f = fminf(f, 1.0f);
    f = fmaxf(f, 1e-8f);
    if (h == 0) out[e] = -logf(f);   // both lanes hold identical f
}

extern "C" void kernel_launch(void* const* d_in, const int* in_sizes, int n_in,
                              void* d_out, int out_size) {
    const int*   contexts = (const int*)d_in[0];   // [B, 10] int32
    const int*   targets  = (const int*)d_in[1];   // [B] int32
    const float* emb      = (const float*)d_in[2]; // [V, 36] float32
    float*       out      = (float*)d_out;         // [B] float32
    const int B = in_sizes[1];                     // 16384
    const int threads = 128;
    const int blocks = (2 * B + threads - 1) / threads;   // 256 blocks
    qcbow_kernel<<<blocks, threads>>>(contexts, targets, emb, out, B);
}